// round 7
// baseline (speedup 1.0000x reference)
#include <cuda_runtime.h>
#include <cuda_fp16.h>
#include <math.h>
#include <stdint.h>

// Problem constants
#define Bz 8
#define Nn 1024
#define Mm 32
#define BN (Bz*Nn)            // 8192
#define KFREQ (-0.6140226914650789f)   // -log(10000)/15

#define NTILES 1024            // 8192 nodes / 8 per tile
#define EDGE_GRID 256          // x4 iterations each, single balanced wave

// Weight image layout (bytes): B1hi | B1lo | B2hi | B2lo   (fp16)
// B1: [128 n][64 k], row stride 72 fp16 (144B)  -> 18432 B each
// B2: [128 n][128 k], row stride 136 fp16 (272B) -> 34816 B each
#define OFF_B1HI 0
#define OFF_B1LO 18432
#define OFF_B2HI 36864
#define OFF_B2LO 71680
#define WIMG_BYTES 106496

// ---------------------------------------------------------------------------
// Scratch
// ---------------------------------------------------------------------------
__device__ float g_p1[BN*128];     // emb @ W1[0:128]
__device__ float g_p2[BN*128];     // emb @ W1[128:256]
__device__ float g_hsum[BN*128];   // sum_j relu-h
__device__ float g_w2x[128*128];   // W2 @ Wx1
__device__ float g_w2h[128*128];   // W2 @ Wh1[128:256]
__device__ float g_b2x[128];       // b2 @ Wx1 + bx1
__device__ float g_bvec[128];      // b2 @ Wh1[128:256]
__device__ uint4 g_Bimg[WIMG_BYTES/16];

// ---------------------------------------------------------------------------
// helpers
// ---------------------------------------------------------------------------
__device__ __forceinline__ uint32_t s2u(const void* p) {
    uint32_t a;
    asm("{ .reg .u64 t; cvta.to.shared.u64 t, %1; cvt.u32.u64 %0, t; }"
        : "=r"(a) : "l"(p));
    return a;
}
__device__ __forceinline__ void ldmx4(uint32_t& r0, uint32_t& r1,
                                      uint32_t& r2, uint32_t& r3, uint32_t addr) {
    asm volatile("ldmatrix.sync.aligned.m8n8.x4.shared.b16 {%0,%1,%2,%3}, [%4];"
                 : "=r"(r0), "=r"(r1), "=r"(r2), "=r"(r3) : "r"(addr));
}
__device__ __forceinline__ void mma16816(float* c, const uint32_t* a,
                                         uint32_t b0, uint32_t b1) {
    asm volatile(
        "mma.sync.aligned.m16n8k16.row.col.f32.f16.f16.f32 "
        "{%0,%1,%2,%3}, {%4,%5,%6,%7}, {%8,%9}, {%0,%1,%2,%3};"
        : "+f"(c[0]), "+f"(c[1]), "+f"(c[2]), "+f"(c[3])
        : "r"(a[0]), "r"(a[1]), "r"(a[2]), "r"(a[3]), "r"(b0), "r"(b1));
}
// pack: lower half = f0, upper = f1
__device__ __forceinline__ uint32_t packhf(float f0, float f1) {
    uint32_t r;
    asm("cvt.rn.f16x2.f32 %0, %1, %2;" : "=r"(r) : "f"(f1), "f"(f0));
    return r;
}
__device__ __forceinline__ float hfr(float x) {
    return __half2float(__float2half_rn(x));
}

// ---------------------------------------------------------------------------
// K-1: fold kernels.  W2x = W2@Wx1, W2h = W2@Wh1b + bias folds.
// ---------------------------------------------------------------------------
__global__ __launch_bounds__(128) void k_fold(
    const float* __restrict__ w2,  const float* __restrict__ b2,
    const float* __restrict__ wx1, const float* __restrict__ bx1,
    const float* __restrict__ wh1)
{
    __shared__ float w2sh[16][128];
    const int c = threadIdx.x;
    const int d0 = blockIdx.x * 16;

    #pragma unroll
    for (int i = 0; i < 16; i++)
        w2sh[i][c] = w2[(d0 + i) * 128 + c];
    __syncthreads();

    float a1[16], a2[16];
    #pragma unroll
    for (int i = 0; i < 16; i++) { a1[i] = 0.f; a2[i] = 0.f; }

    #pragma unroll 2
    for (int k = 0; k < 128; k++) {
        float wA = wx1[k * 128 + c];
        float wB = wh1[(128 + k) * 128 + c];
        #pragma unroll
        for (int i = 0; i < 16; i++) {
            float v = w2sh[i][k];
            a1[i] = fmaf(v, wA, a1[i]);
            a2[i] = fmaf(v, wB, a2[i]);
        }
    }
    #pragma unroll
    for (int i = 0; i < 16; i++) {
        g_w2x[(d0 + i) * 128 + c] = a1[i];
        g_w2h[(d0 + i) * 128 + c] = a2[i];
    }

    if (blockIdx.x == 0) {
        float s1 = bx1[c], s2 = 0.f;
        for (int k = 0; k < 128; k++) {
            float bk = b2[k];
            s1 = fmaf(bk, wx1[k * 128 + c], s1);
            s2 = fmaf(bk, wh1[(128 + k) * 128 + c], s2);
        }
        g_b2x[c]  = s1;
        g_bvec[c] = s2;
    }
}

// ---------------------------------------------------------------------------
// K-0.5: weight image prep (fp16 hi/lo of B^T, padded layouts for ldmatrix)
// ---------------------------------------------------------------------------
__global__ void k_prep(const float* __restrict__ w1)
{
    unsigned char* img = (unsigned char*)g_Bimg;
    int i = blockIdx.x * blockDim.x + threadIdx.x;
    if (i < 8192) {
        int n = i & 127, k = i >> 7;            // k 0..63
        float v = w1[(256 + k) * 128 + n];
        float hv = hfr(v);
        uint32_t b = (uint32_t)(n * 144 + k * 2);
        *(__half*)(img + OFF_B1HI + b) = __float2half_rn(v);
        *(__half*)(img + OFF_B1LO + b) = __float2half_rn(v - hv);
    } else if (i < 24576) {
        int e = i - 8192;
        int n = e & 127, k = e >> 7;            // k 0..127
        float v = g_w2x[k * 128 + n];
        float hv = hfr(v);
        uint32_t b = (uint32_t)(n * 272 + k * 2);
        *(__half*)(img + OFF_B2HI + b) = __float2half_rn(v);
        *(__half*)(img + OFF_B2LO + b) = __float2half_rn(v - hv);
    }
}

// ---------------------------------------------------------------------------
// K0: per-node projections p1, p2.  8 nodes per block, 128 threads.
// ---------------------------------------------------------------------------
__global__ __launch_bounds__(128) void k_proj(
    const float* __restrict__ emb, const float* __restrict__ w1)
{
    __shared__ float esh[8][128];
    const int c = threadIdx.x;
    const int n0 = blockIdx.x * 8;

    #pragma unroll
    for (int i = 0; i < 8; i++)
        esh[i][c] = emb[(n0 + i) * 128 + c];
    __syncthreads();

    float a1[8], a2[8];
    #pragma unroll
    for (int i = 0; i < 8; i++) { a1[i] = 0.f; a2[i] = 0.f; }

    #pragma unroll 4
    for (int d = 0; d < 128; d++) {
        float wA = w1[d * 128 + c];
        float wB = w1[(128 + d) * 128 + c];
        #pragma unroll
        for (int i = 0; i < 8; i++) {
            float e = esh[i][d];
            a1[i] = fmaf(e, wA, a1[i]);
            a2[i] = fmaf(e, wB, a2[i]);
        }
    }
    #pragma unroll
    for (int i = 0; i < 8; i++) {
        g_p1[(n0 + i) * 128 + c] = a1[i];
        g_p2[(n0 + i) * 128 + c] = a2[i];
    }
}

// ---------------------------------------------------------------------------
// K1: HMMA edge kernel.  256 threads (8 warps), warp = node, 8 nodes/iter.
// fp16 A (single), fp16 B split hi/lo -> 2 MMAs per fragment; ldmatrix.x4.
// ---------------------------------------------------------------------------
__global__ __launch_bounds__(256) void k_edge(
    const float* __restrict__ coords,
    const float* __restrict__ edges,
    const float* __restrict__ b1g,
    const float* __restrict__ wx2, const float* __restrict__ bx2,
    const int* __restrict__ ids,
    float* __restrict__ out_coords)
{
    extern __shared__ unsigned char wsm[];     // weight images
    const uint32_t sb    = s2u(wsm);
    const uint32_t b1hiA = sb + OFF_B1HI;
    const uint32_t b1loA = sb + OFF_B1LO;
    const uint32_t b2hiA = sb + OFF_B2HI;
    const uint32_t b2loA = sb + OFF_B2LO;

    __shared__ float dist_sh[256];
    __shared__ float unit_sh[256][3];
    __shared__ int   jid_sh[256];
    __shared__ float px_sh[256];
    __shared__ float b1_sh[128], b2x_sh[128], wx2_sh[128], fr_sh[16];

    const int tid  = threadIdx.x;
    const int w    = tid >> 5;
    const int lane = tid & 31;
    const int td4  = lane >> 2;
    const int tm4  = lane & 3;

    { // weights gmem -> smem
        uint4* dst = (uint4*)wsm;
        for (int i = tid; i < WIMG_BYTES / 16; i += 256) dst[i] = g_Bimg[i];
    }
    if (tid < 128) {
        b1_sh[tid]  = b1g[tid];
        b2x_sh[tid] = g_b2x[tid];
        wx2_sh[tid] = wx2[tid];
    }
    if (tid < 16) fr_sh[tid] = expf((float)tid * KFREQ);
    __syncthreads();

    const float fr0 = fr_sh[2 * tm4],     fr1 = fr_sh[2 * tm4 + 1];
    const float fr2 = fr_sh[2 * tm4 + 8], fr3 = fr_sh[2 * tm4 + 9];
    const float bx2v = bx2[0];

    for (int tile = blockIdx.x; tile < NTILES; tile += EDGE_GRID) {
        const int gE0   = tile * 256;
        const int node0 = tile * 8;

        // per-edge setup: dist, unit, gathered neighbor id (1 thread/edge)
        {
            int e = tid;
            int nd = node0 + (e >> 5), m = e & 31;
            int jabs = ((nd >> 10) << 10) + ids[nd * 32 + m];
            jid_sh[e] = jabs;
            float dx = coords[nd * 3 + 0] - coords[jabs * 3 + 0];
            float dy = coords[nd * 3 + 1] - coords[jabs * 3 + 1];
            float dz = coords[nd * 3 + 2] - coords[jabs * 3 + 2];
            float d = sqrtf(dx * dx + dy * dy + dz * dz);
            dist_sh[e] = d;
            float inv = (d > 0.f) ? (1.f / d) : 0.f;
            unit_sh[e][0] = dx * inv;
            unit_sh[e][1] = dy * inv;
            unit_sh[e][2] = dz * inv;
        }
        __syncthreads();

        const int node = node0 + w;
        float dloc[4];
        #pragma unroll
        for (int i = 0; i < 4; i++) dloc[i] = dist_sh[w * 32 + td4 + 8 * i];

        // ---------------- GEMM1: C1 = F @ W1c ----------------
        float c1[2][16][4];
        #pragma unroll
        for (int mt = 0; mt < 2; mt++)
        #pragma unroll
        for (int nt = 0; nt < 16; nt++)
        #pragma unroll
        for (int q = 0; q < 4; q++) c1[mt][nt][q] = 0.f;

        #pragma unroll
        for (int kt = 0; kt < 4; kt++) {
            uint32_t ahi[2][4];
            #pragma unroll
            for (int i = 0; i < 4; i++) {
                float v0, v1, v2, v3;
                if (kt == 0) {
                    v0 = __sinf(dloc[i] * fr0); v1 = __sinf(dloc[i] * fr1);
                    v2 = __sinf(dloc[i] * fr2); v3 = __sinf(dloc[i] * fr3);
                } else if (kt == 1) {
                    v0 = __cosf(dloc[i] * fr0); v1 = __cosf(dloc[i] * fr1);
                    v2 = __cosf(dloc[i] * fr2); v3 = __cosf(dloc[i] * fr3);
                } else {
                    const float* ep = edges
                        + (size_t)(gE0 + w * 32 + td4 + 8 * i) * 32
                        + (kt - 2) * 16 + 2 * tm4;
                    float2 va = *(const float2*)ep;
                    float2 vb = *(const float2*)(ep + 8);
                    v0 = va.x; v1 = va.y; v2 = vb.x; v3 = vb.y;
                }
                int mt = i >> 1, s = i & 1;
                ahi[mt][s]     = packhf(v0, v1);
                ahi[mt][2 + s] = packhf(v2, v3);
            }
            // B fragments: .x4 fetches two adjacent nt tiles per instruction.
            // lane>>3 = q selects (ntq = nt2*2 + (q>>1), khalf = q&1).
            const int qsel  = lane >> 3;
            const int ntoff = qsel >> 1;
            const int khalf = qsel & 1;
            #pragma unroll
            for (int nt2 = 0; nt2 < 8; nt2++) {
                const int ntq = 2 * nt2 + ntoff;
                uint32_t off = (uint32_t)((ntq * 8 + (lane & 7)) * 72
                                          + kt * 16 + khalf * 8) * 2;
                uint32_t p0, p1, p2, p3, q0, q1, q2, q3;
                ldmx4(p0, p1, p2, p3, b1hiA + off);
                ldmx4(q0, q1, q2, q3, b1loA + off);
                #pragma unroll
                for (int mt = 0; mt < 2; mt++) {
                    mma16816(c1[mt][2 * nt2 + 0], ahi[mt], p0, p1);
                    mma16816(c1[mt][2 * nt2 + 0], ahi[mt], q0, q1);
                    mma16816(c1[mt][2 * nt2 + 1], ahi[mt], p2, p3);
                    mma16816(c1[mt][2 * nt2 + 1], ahi[mt], q2, q3);
                }
            }
        }

        // ------- epilogue1: +p1+p2+b1, relu, hsum, pack h -> A2 frags -------
        uint32_t a2[2][8][4];
        #pragma unroll
        for (int kt2 = 0; kt2 < 8; kt2++) {
            #pragma unroll
            for (int sub = 0; sub < 2; sub++) {
                const int nt = 2 * kt2 + sub;
                const int n0c = nt * 8 + 2 * tm4;
                const float pa0 = g_p1[(size_t)node * 128 + n0c];
                const float pa1 = g_p1[(size_t)node * 128 + n0c + 1];
                const float bb0 = b1_sh[n0c], bb1 = b1_sh[n0c + 1];
                float hs0 = 0.f, hs1 = 0.f;
                #pragma unroll
                for (int mt = 0; mt < 2; mt++) {
                    #pragma unroll
                    for (int half = 0; half < 2; half++) {
                        int j = jid_sh[w * 32 + td4 + 8 * (2 * mt + half)];
                        float p20 = g_p2[(size_t)j * 128 + n0c];
                        float p21 = g_p2[(size_t)j * 128 + n0c + 1];
                        float h0 = fmaxf(c1[mt][nt][2 * half + 0] + pa0 + p20 + bb0, 0.f);
                        float h1 = fmaxf(c1[mt][nt][2 * half + 1] + pa1 + p21 + bb1, 0.f);
                        hs0 += h0; hs1 += h1;
                        a2[mt][kt2][half + 2 * sub] = packhf(h0, h1);
                    }
                }
                // reduce hsum over the warp's 32 rows (lanes sharing tm4)
                #pragma unroll
                for (int o = 4; o < 32; o <<= 1) {
                    hs0 += __shfl_xor_sync(0xffffffffu, hs0, o);
                    hs1 += __shfl_xor_sync(0xffffffffu, hs1, o);
                }
                if (td4 == 0) {
                    g_hsum[(size_t)node * 128 + n0c]     = hs0;
                    g_hsum[(size_t)node * 128 + n0c + 1] = hs1;
                }
            }
        }

        // ---------------- GEMM2 (two N-halves): C2 = h @ W2x ----------------
        float px[4] = {0.f, 0.f, 0.f, 0.f};
        #pragma unroll
        for (int half = 0; half < 2; half++) {
            float c2[2][8][4];
            #pragma unroll
            for (int mt = 0; mt < 2; mt++)
            #pragma unroll
            for (int nl = 0; nl < 8; nl++)
            #pragma unroll
            for (int q = 0; q < 4; q++) c2[mt][nl][q] = 0.f;

            const int qsel  = lane >> 3;
            const int nloff = qsel >> 1;
            const int khalf = qsel & 1;
            #pragma unroll
            for (int kt2 = 0; kt2 < 8; kt2++) {
                #pragma unroll
                for (int nl2 = 0; nl2 < 4; nl2++) {
                    const int ntq = half * 8 + 2 * nl2 + nloff;
                    uint32_t off = (uint32_t)((ntq * 8 + (lane & 7)) * 136
                                              + kt2 * 16 + khalf * 8) * 2;
                    uint32_t p0, p1, p2, p3, q0, q1, q2, q3;
                    ldmx4(p0, p1, p2, p3, b2hiA + off);
                    ldmx4(q0, q1, q2, q3, b2loA + off);
                    #pragma unroll
                    for (int mt = 0; mt < 2; mt++) {
                        mma16816(c2[mt][2 * nl2 + 0], a2[mt][kt2], p0, p1);
                        mma16816(c2[mt][2 * nl2 + 0], a2[mt][kt2], q0, q1);
                        mma16816(c2[mt][2 * nl2 + 1], a2[mt][kt2], p2, p3);
                        mma16816(c2[mt][2 * nl2 + 1], a2[mt][kt2], q2, q3);
                    }
                }
            }
            // epilogue2: t = relu(c2 + b2x); px += t * wx2
            #pragma unroll
            for (int nl = 0; nl < 8; nl++) {
                const int n = half * 64 + nl * 8 + 2 * tm4;
                const float bA = b2x_sh[n], bB = b2x_sh[n + 1];
                const float wA = wx2_sh[n], wB = wx2_sh[n + 1];
                #pragma unroll
                for (int mt = 0; mt < 2; mt++) {
                    px[2 * mt + 0] = fmaf(fmaxf(c2[mt][nl][0] + bA, 0.f), wA,
                                     fmaf(fmaxf(c2[mt][nl][1] + bB, 0.f), wB,
                                          px[2 * mt + 0]));
                    px[2 * mt + 1] = fmaf(fmaxf(c2[mt][nl][2] + bA, 0.f), wA,
                                     fmaf(fmaxf(c2[mt][nl][3] + bB, 0.f), wB,
                                          px[2 * mt + 1]));
                }
            }
        }

        // reduce px across the 4 lanes sharing td4, then coord update
        #pragma unroll
        for (int i = 0; i < 4; i++) {
            px[i] += __shfl_xor_sync(0xffffffffu, px[i], 1);
            px[i] += __shfl_xor_sync(0xffffffffu, px[i], 2);
            px[i] += bx2v;
        }
        if (tm4 == 0) {
            #pragma unroll
            for (int i = 0; i < 4; i++)
                px_sh[w * 32 + td4 + 8 * i] = px[i];
        }
        __syncwarp();
        {
            int e = w * 32 + lane;
            float p = px_sh[e];
            float sx = unit_sh[e][0] * p;
            float sy = unit_sh[e][1] * p;
            float sz = unit_sh[e][2] * p;
            #pragma unroll
            for (int o = 16; o > 0; o >>= 1) {
                sx += __shfl_xor_sync(0xffffffffu, sx, o);
                sy += __shfl_xor_sync(0xffffffffu, sy, o);
                sz += __shfl_xor_sync(0xffffffffu, sz, o);
            }
            if (lane == 0) {
                out_coords[node * 3 + 0] = coords[node * 3 + 0] + sx * (1.f / 32.f);
                out_coords[node * 3 + 1] = coords[node * 3 + 1] + sy * (1.f / 32.f);
                out_coords[node * 3 + 2] = coords[node * 3 + 2] + sz * (1.f / 32.f);
            }
        }
        __syncthreads();
    }
}

// ---------------------------------------------------------------------------
// K3: node update MLP with W2 folded.  8 nodes per block, 128 threads.
// ---------------------------------------------------------------------------
__global__ __launch_bounds__(128) void k_node(
    const float* __restrict__ emb,
    const float* __restrict__ mask,
    const float* __restrict__ wh1, const float* __restrict__ bh1,
    const float* __restrict__ wh2, const float* __restrict__ bh2,
    float* __restrict__ out_emb)
{
    __shared__ float esh[8][128];
    __shared__ float hsh[8][128];
    __shared__ float ph[8][128];
    __shared__ float msk[8];
    const int c = threadIdx.x;
    const int n0 = blockIdx.x * 8;

    if (c < 8) msk[c] = mask[n0 + c];
    __syncthreads();
    #pragma unroll
    for (int i = 0; i < 8; i++) {
        esh[i][c] = emb[(n0 + i) * 128 + c];
        hsh[i][c] = g_hsum[(n0 + i) * 128 + c] * (msk[i] * (1.f / 32.f));
    }
    __syncthreads();

    float acc[8];
    {
        float bc = bh1[c];
        float bv = g_bvec[c];
        #pragma unroll
        for (int i = 0; i < 8; i++) acc[i] = bc + msk[i] * bv;
        #pragma unroll 4
        for (int k = 0; k < 128; k += 2) {
            float wa0 = wh1[(k + 0) * 128 + c];
            float wa1 = wh1[(k + 1) * 128 + c];
            float wb0 = g_w2h[(k + 0) * 128 + c];
            float wb1 = g_w2h[(k + 1) * 128 + c];
            #pragma unroll
            for (int i = 0; i < 8; i++) {
                acc[i] = fmaf(esh[i][k],     wa0,
                         fmaf(esh[i][k + 1], wa1,
                         fmaf(hsh[i][k],     wb0,
                         fmaf(hsh[i][k + 1], wb1, acc[i]))));
            }
        }
        #pragma unroll
        for (int i = 0; i < 8; i++) ph[i][c] = fmaxf(acc[i], 0.f);
    }
    __syncthreads();

    float acc2[8];
    {
        float bc = bh2[c];
        #pragma unroll
        for (int i = 0; i < 8; i++) acc2[i] = bc;
        #pragma unroll 4
        for (int p = 0; p < 128; p += 4) {
            float w0  = wh2[(p + 0) * 128 + c];
            float w1v = wh2[(p + 1) * 128 + c];
            float w2v = wh2[(p + 2) * 128 + c];
            float w3  = wh2[(p + 3) * 128 + c];
            #pragma unroll
            for (int i = 0; i < 8; i++) {
                float4 hv = *(const float4*)&ph[i][p];
                acc2[i] = fmaf(hv.x, w0,
                          fmaf(hv.y, w1v,
                          fmaf(hv.z, w2v,
                          fmaf(hv.w, w3, acc2[i]))));
            }
        }
    }
    #pragma unroll
    for (int i = 0; i < 8; i++)
        out_emb[(n0 + i) * 128 + c] = esh[i][c] + acc2[i];
}

// ---------------------------------------------------------------------------
extern "C" void kernel_launch(void* const* d_in, const int* in_sizes, int n_in,
                              void* d_out, int out_size)
{
    const float* emb    = (const float*)d_in[0];
    const float* coords = (const float*)d_in[1];
    const float* mask   = (const float*)d_in[2];
    const float* edges  = (const float*)d_in[3];
    const float* we_w1  = (const float*)d_in[4];
    const float* we_b1  = (const float*)d_in[5];
    const float* we_w2  = (const float*)d_in[6];
    const float* we_b2  = (const float*)d_in[7];
    const float* wx_w1  = (const float*)d_in[8];
    const float* wx_b1  = (const float*)d_in[9];
    const float* wx_w2  = (const float*)d_in[10];
    const float* wx_b2  = (const float*)d_in[11];
    const float* wh_w1  = (const float*)d_in[12];
    const float* wh_b1  = (const float*)d_in[13];
    const float* wh_w2  = (const float*)d_in[14];
    const float* wh_b2  = (const float*)d_in[15];
    const int*   ids    = (const int*)d_in[16];

    float* out_emb    = (float*)d_out;
    float* out_coords = (float*)d_out + (size_t)BN * 128;

    static int attr_set = 0;
    if (!attr_set) {
        cudaFuncSetAttribute(k_edge,
                             cudaFuncAttributeMaxDynamicSharedMemorySize,
                             WIMG_BYTES);
        attr_set = 1;
    }

    k_fold<<<8, 128>>>(we_w2, we_b2, wx_w1, wx_b1, wh_w1);
    k_prep<<<96, 256>>>(we_w1);
    k_proj<<<BN / 8, 128>>>(emb, we_w1);

    k_edge<<<EDGE_GRID, 256, WIMG_BYTES>>>(coords, edges, we_b1,
                                           wx_w2, wx_b2, ids, out_coords);

    k_node<<<BN / 8, 128>>>(emb, mask, wh_w1, wh_b1, wh_w2, wh_b2, out_emb);
}

// round 8
// speedup vs baseline: 1.0816x; 1.0816x over previous
#include <cuda_runtime.h>
#include <cuda_fp16.h>
#include <math.h>
#include <stdint.h>

// Problem constants
#define Bz 8
#define Nn 1024
#define Mm 32
#define BN (Bz*Nn)            // 8192
#define KFREQ (-0.6140226914650789f)   // -log(10000)/15

#define EDGE_GRID 148
#define WARPS_PER_CTA 12
#define NODES_PER_ITER (EDGE_GRID * WARPS_PER_CTA)   // 1776
#define NITER 5                                       // ceil(8192/1776)

// Weight image layout (bytes): B1hi | B1lo | B2hi | B2lo   (fp16)
// B1: [128 n][64 k], row stride 72 fp16 (144B)  -> 18432 B each
// B2: [128 n][128 k], row stride 136 fp16 (272B) -> 34816 B each
#define OFF_B1HI 0
#define OFF_B1LO 18432
#define OFF_B2HI 36864
#define OFF_B2LO 71680
#define WIMG_BYTES 106496

// ---------------------------------------------------------------------------
// Scratch
// ---------------------------------------------------------------------------
__device__ float g_p1[BN*128];     // emb @ W1[0:128]
__device__ float g_p2[BN*128];     // emb @ W1[128:256]
__device__ float g_hsum[BN*128];   // sum_j relu-h
__device__ float g_w2x[128*128];   // W2 @ Wx1
__device__ float g_w2h[128*128];   // W2 @ Wh1[128:256]
__device__ float g_b2x[128];       // b2 @ Wx1 + bx1
__device__ float g_bvec[128];      // b2 @ Wh1[128:256]
__device__ uint4 g_Bimg[WIMG_BYTES/16];

// ---------------------------------------------------------------------------
// helpers
// ---------------------------------------------------------------------------
__device__ __forceinline__ uint32_t s2u(const void* p) {
    uint32_t a;
    asm("{ .reg .u64 t; cvta.to.shared.u64 t, %1; cvt.u32.u64 %0, t; }"
        : "=r"(a) : "l"(p));
    return a;
}
__device__ __forceinline__ void ldmx4(uint32_t& r0, uint32_t& r1,
                                      uint32_t& r2, uint32_t& r3, uint32_t addr) {
    asm volatile("ldmatrix.sync.aligned.m8n8.x4.shared.b16 {%0,%1,%2,%3}, [%4];"
                 : "=r"(r0), "=r"(r1), "=r"(r2), "=r"(r3) : "r"(addr));
}
__device__ __forceinline__ void mma16816(float* c, const uint32_t* a,
                                         uint32_t b0, uint32_t b1) {
    asm volatile(
        "mma.sync.aligned.m16n8k16.row.col.f32.f16.f16.f32 "
        "{%0,%1,%2,%3}, {%4,%5,%6,%7}, {%8,%9}, {%0,%1,%2,%3};"
        : "+f"(c[0]), "+f"(c[1]), "+f"(c[2]), "+f"(c[3])
        : "r"(a[0]), "r"(a[1]), "r"(a[2]), "r"(a[3]), "r"(b0), "r"(b1));
}
// pack: lower half = f0, upper = f1
__device__ __forceinline__ uint32_t packhf(float f0, float f1) {
    uint32_t r;
    asm("cvt.rn.f16x2.f32 %0, %1, %2;" : "=r"(r) : "f"(f1), "f"(f0));
    return r;
}
__device__ __forceinline__ float hfr(float x) {
    return __half2float(__float2half_rn(x));
}

// ---------------------------------------------------------------------------
// K-1: fold kernels.  W2x = W2@Wx1, W2h = W2@Wh1b + bias folds.
// ---------------------------------------------------------------------------
__global__ __launch_bounds__(128) void k_fold(
    const float* __restrict__ w2,  const float* __restrict__ b2,
    const float* __restrict__ wx1, const float* __restrict__ bx1,
    const float* __restrict__ wh1)
{
    __shared__ float w2sh[16][128];
    const int c = threadIdx.x;
    const int d0 = blockIdx.x * 16;

    #pragma unroll
    for (int i = 0; i < 16; i++)
        w2sh[i][c] = w2[(d0 + i) * 128 + c];
    __syncthreads();

    float a1[16], a2[16];
    #pragma unroll
    for (int i = 0; i < 16; i++) { a1[i] = 0.f; a2[i] = 0.f; }

    #pragma unroll 2
    for (int k = 0; k < 128; k++) {
        float wA = wx1[k * 128 + c];
        float wB = wh1[(128 + k) * 128 + c];
        #pragma unroll
        for (int i = 0; i < 16; i++) {
            float v = w2sh[i][k];
            a1[i] = fmaf(v, wA, a1[i]);
            a2[i] = fmaf(v, wB, a2[i]);
        }
    }
    #pragma unroll
    for (int i = 0; i < 16; i++) {
        g_w2x[(d0 + i) * 128 + c] = a1[i];
        g_w2h[(d0 + i) * 128 + c] = a2[i];
    }

    if (blockIdx.x == 0) {
        float s1 = bx1[c], s2 = 0.f;
        for (int k = 0; k < 128; k++) {
            float bk = b2[k];
            s1 = fmaf(bk, wx1[k * 128 + c], s1);
            s2 = fmaf(bk, wh1[(128 + k) * 128 + c], s2);
        }
        g_b2x[c]  = s1;
        g_bvec[c] = s2;
    }
}

// ---------------------------------------------------------------------------
// K-0.5: weight image prep (fp16 hi/lo of B^T, padded layouts for ldmatrix)
// ---------------------------------------------------------------------------
__global__ void k_prep(const float* __restrict__ w1)
{
    unsigned char* img = (unsigned char*)g_Bimg;
    int i = blockIdx.x * blockDim.x + threadIdx.x;
    if (i < 8192) {
        int n = i & 127, k = i >> 7;            // k 0..63
        float v = w1[(256 + k) * 128 + n];
        float hv = hfr(v);
        uint32_t b = (uint32_t)(n * 144 + k * 2);
        *(__half*)(img + OFF_B1HI + b) = __float2half_rn(v);
        *(__half*)(img + OFF_B1LO + b) = __float2half_rn(v - hv);
    } else if (i < 24576) {
        int e = i - 8192;
        int n = e & 127, k = e >> 7;            // k 0..127
        float v = g_w2x[k * 128 + n];
        float hv = hfr(v);
        uint32_t b = (uint32_t)(n * 272 + k * 2);
        *(__half*)(img + OFF_B2HI + b) = __float2half_rn(v);
        *(__half*)(img + OFF_B2LO + b) = __float2half_rn(v - hv);
    }
}

// ---------------------------------------------------------------------------
// K0: per-node projections p1, p2.  8 nodes per block, 128 threads.
// ---------------------------------------------------------------------------
__global__ __launch_bounds__(128) void k_proj(
    const float* __restrict__ emb, const float* __restrict__ w1)
{
    __shared__ float esh[8][128];
    const int c = threadIdx.x;
    const int n0 = blockIdx.x * 8;

    #pragma unroll
    for (int i = 0; i < 8; i++)
        esh[i][c] = emb[(n0 + i) * 128 + c];
    __syncthreads();

    float a1[8], a2[8];
    #pragma unroll
    for (int i = 0; i < 8; i++) { a1[i] = 0.f; a2[i] = 0.f; }

    #pragma unroll 4
    for (int d = 0; d < 128; d++) {
        float wA = w1[d * 128 + c];
        float wB = w1[(128 + d) * 128 + c];
        #pragma unroll
        for (int i = 0; i < 8; i++) {
            float e = esh[i][d];
            a1[i] = fmaf(e, wA, a1[i]);
            a2[i] = fmaf(e, wB, a2[i]);
        }
    }
    #pragma unroll
    for (int i = 0; i < 8; i++) {
        g_p1[(n0 + i) * 128 + c] = a1[i];
        g_p2[(n0 + i) * 128 + c] = a2[i];
    }
}

// ---------------------------------------------------------------------------
// K1: HMMA edge kernel.  384 threads (12 warps), warp = node.
// Register-economy version: GEMM1 in two N-halves, GEMM2 in N-quarters.
// ---------------------------------------------------------------------------
__global__ __launch_bounds__(384, 1) void k_edge(
    const float* __restrict__ coords,
    const float* __restrict__ edges,
    const float* __restrict__ b1g,
    const float* __restrict__ wx2, const float* __restrict__ bx2,
    const int* __restrict__ ids,
    float* __restrict__ out_coords)
{
    extern __shared__ unsigned char wsm[];     // weight images
    const uint32_t sb    = s2u(wsm);
    const uint32_t b1hiA = sb + OFF_B1HI;
    const uint32_t b1loA = sb + OFF_B1LO;
    const uint32_t b2hiA = sb + OFF_B2HI;
    const uint32_t b2loA = sb + OFF_B2LO;

    __shared__ float dist_sh[384];
    __shared__ float unit_sh[384][3];
    __shared__ int   jid_sh[384];
    __shared__ float px_sh[384];
    __shared__ float b1_sh[128], b2x_sh[128], wx2_sh[128], fr_sh[16];

    const int tid  = threadIdx.x;
    const int w    = tid >> 5;
    const int lane = tid & 31;
    const int td4  = lane >> 2;
    const int tm4  = lane & 3;

    { // weights gmem -> smem
        uint4* dst = (uint4*)wsm;
        for (int i = tid; i < WIMG_BYTES / 16; i += 384) dst[i] = g_Bimg[i];
    }
    if (tid < 128) {
        b1_sh[tid]  = b1g[tid];
        b2x_sh[tid] = g_b2x[tid];
        wx2_sh[tid] = wx2[tid];
    }
    if (tid < 16) fr_sh[tid] = expf((float)tid * KFREQ);
    __syncthreads();

    const float fr0 = fr_sh[2 * tm4],     fr1 = fr_sh[2 * tm4 + 1];
    const float fr2 = fr_sh[2 * tm4 + 8], fr3 = fr_sh[2 * tm4 + 9];
    const float bx2v = bx2[0];

    const int qsel  = lane >> 3;
    const int ntoff = qsel >> 1;
    const int khalf = qsel & 1;

    for (int it = 0; it < NITER; it++) {
        const int nodebase = it * NODES_PER_ITER + blockIdx.x * WARPS_PER_CTA;

        // per-edge setup: dist, unit, gathered neighbor id (1 thread/edge)
        {
            int nd = nodebase + (tid >> 5);
            if (nd < BN) {
                int m = tid & 31;
                int jabs = ((nd >> 10) << 10) + ids[nd * 32 + m];
                jid_sh[tid] = jabs;
                float dx = coords[nd * 3 + 0] - coords[jabs * 3 + 0];
                float dy = coords[nd * 3 + 1] - coords[jabs * 3 + 1];
                float dz = coords[nd * 3 + 2] - coords[jabs * 3 + 2];
                float d = sqrtf(dx * dx + dy * dy + dz * dz);
                dist_sh[tid] = d;
                float inv = (d > 0.f) ? (1.f / d) : 0.f;
                unit_sh[tid][0] = dx * inv;
                unit_sh[tid][1] = dy * inv;
                unit_sh[tid][2] = dz * inv;
            }
        }
        __syncthreads();

        const int node = nodebase + w;
        if (node < BN) {
            float dloc[4];
            #pragma unroll
            for (int i = 0; i < 4; i++) dloc[i] = dist_sh[w * 32 + td4 + 8 * i];

            // A fragments for GEMM1 (kept across both N-halves): 32 regs
            uint32_t ahi[4][2][4];
            #pragma unroll
            for (int kt = 0; kt < 4; kt++) {
                #pragma unroll
                for (int i = 0; i < 4; i++) {
                    float v0, v1, v2, v3;
                    if (kt == 0) {
                        v0 = __sinf(dloc[i] * fr0); v1 = __sinf(dloc[i] * fr1);
                        v2 = __sinf(dloc[i] * fr2); v3 = __sinf(dloc[i] * fr3);
                    } else if (kt == 1) {
                        v0 = __cosf(dloc[i] * fr0); v1 = __cosf(dloc[i] * fr1);
                        v2 = __cosf(dloc[i] * fr2); v3 = __cosf(dloc[i] * fr3);
                    } else {
                        const float* ep = edges
                            + (size_t)(node * 32 + td4 + 8 * i) * 32
                            + (kt - 2) * 16 + 2 * tm4;
                        float2 va = *(const float2*)ep;
                        float2 vb = *(const float2*)(ep + 8);
                        v0 = va.x; v1 = va.y; v2 = vb.x; v3 = vb.y;
                    }
                    int mt = i >> 1, s = i & 1;
                    ahi[kt][mt][s]     = packhf(v0, v1);
                    ahi[kt][mt][2 + s] = packhf(v2, v3);
                }
            }

            // ---------------- GEMM1 + epilogue1, two N-halves ----------------
            uint32_t a2[2][8][4];
            #pragma unroll
            for (int half = 0; half < 2; half++) {
                float c1h[2][8][4];
                #pragma unroll
                for (int mt = 0; mt < 2; mt++)
                #pragma unroll
                for (int nt = 0; nt < 8; nt++)
                #pragma unroll
                for (int q = 0; q < 4; q++) c1h[mt][nt][q] = 0.f;

                #pragma unroll
                for (int kt = 0; kt < 4; kt++) {
                    #pragma unroll
                    for (int nt2 = 0; nt2 < 4; nt2++) {
                        const int ntq = half * 8 + 2 * nt2 + ntoff;
                        uint32_t off = (uint32_t)((ntq * 8 + (lane & 7)) * 72
                                                  + kt * 16 + khalf * 8) * 2;
                        uint32_t p0, p1, p2, p3, q0, q1, q2, q3;
                        ldmx4(p0, p1, p2, p3, b1hiA + off);
                        ldmx4(q0, q1, q2, q3, b1loA + off);
                        #pragma unroll
                        for (int mt = 0; mt < 2; mt++) {
                            mma16816(c1h[mt][2 * nt2 + 0], ahi[kt][mt], p0, p1);
                            mma16816(c1h[mt][2 * nt2 + 0], ahi[kt][mt], q0, q1);
                            mma16816(c1h[mt][2 * nt2 + 1], ahi[kt][mt], p2, p3);
                            mma16816(c1h[mt][2 * nt2 + 1], ahi[kt][mt], q2, q3);
                        }
                    }
                }

                // epilogue1 for this half: nt = half*8 + ntl
                #pragma unroll
                for (int kt2l = 0; kt2l < 4; kt2l++) {
                    #pragma unroll
                    for (int sub = 0; sub < 2; sub++) {
                        const int ntl = 2 * kt2l + sub;
                        const int n0c = (half * 8 + ntl) * 8 + 2 * tm4;
                        float2 pa = *(const float2*)(g_p1 + (size_t)node * 128 + n0c);
                        const float bb0 = b1_sh[n0c], bb1 = b1_sh[n0c + 1];
                        float hs0 = 0.f, hs1 = 0.f;
                        #pragma unroll
                        for (int mt = 0; mt < 2; mt++) {
                            #pragma unroll
                            for (int mh = 0; mh < 2; mh++) {
                                int j = jid_sh[w * 32 + td4 + 8 * (2 * mt + mh)];
                                float2 p2v = *(const float2*)(g_p2 + (size_t)j * 128 + n0c);
                                float h0 = fmaxf(c1h[mt][ntl][2 * mh + 0] + pa.x + p2v.x + bb0, 0.f);
                                float h1 = fmaxf(c1h[mt][ntl][2 * mh + 1] + pa.y + p2v.y + bb1, 0.f);
                                hs0 += h0; hs1 += h1;
                                a2[mt][half * 4 + kt2l][mh + 2 * sub] = packhf(h0, h1);
                            }
                        }
                        // reduce hsum over the warp's 32 rows (lanes sharing tm4)
                        #pragma unroll
                        for (int o = 4; o < 32; o <<= 1) {
                            hs0 += __shfl_xor_sync(0xffffffffu, hs0, o);
                            hs1 += __shfl_xor_sync(0xffffffffu, hs1, o);
                        }
                        if (td4 == 0) {
                            g_hsum[(size_t)node * 128 + n0c]     = hs0;
                            g_hsum[(size_t)node * 128 + n0c + 1] = hs1;
                        }
                    }
                }
            }

            // ---------------- GEMM2 in N-quarters: C2 = h @ W2x ----------------
            float px[4] = {0.f, 0.f, 0.f, 0.f};
            #pragma unroll
            for (int half = 0; half < 2; half++) {
                #pragma unroll
                for (int q4 = 0; q4 < 2; q4++) {
                    float c2q[2][4][4];
                    #pragma unroll
                    for (int mt = 0; mt < 2; mt++)
                    #pragma unroll
                    for (int nl = 0; nl < 4; nl++)
                    #pragma unroll
                    for (int q = 0; q < 4; q++) c2q[mt][nl][q] = 0.f;

                    #pragma unroll
                    for (int kt2 = 0; kt2 < 8; kt2++) {
                        #pragma unroll
                        for (int nl2 = 0; nl2 < 2; nl2++) {
                            const int ntq = half * 8 + q4 * 4 + 2 * nl2 + ntoff;
                            uint32_t off = (uint32_t)((ntq * 8 + (lane & 7)) * 136
                                                      + kt2 * 16 + khalf * 8) * 2;
                            uint32_t p0, p1, p2, p3, q0, q1, q2, q3;
                            ldmx4(p0, p1, p2, p3, b2hiA + off);
                            ldmx4(q0, q1, q2, q3, b2loA + off);
                            #pragma unroll
                            for (int mt = 0; mt < 2; mt++) {
                                mma16816(c2q[mt][2 * nl2 + 0], a2[mt][kt2], p0, p1);
                                mma16816(c2q[mt][2 * nl2 + 0], a2[mt][kt2], q0, q1);
                                mma16816(c2q[mt][2 * nl2 + 1], a2[mt][kt2], p2, p3);
                                mma16816(c2q[mt][2 * nl2 + 1], a2[mt][kt2], q2, q3);
                            }
                        }
                    }
                    // epilogue2 quarter: t = relu(c2 + b2x); px += t * wx2
                    #pragma unroll
                    for (int nl = 0; nl < 4; nl++) {
                        const int n = half * 64 + q4 * 32 + nl * 8 + 2 * tm4;
                        const float bA = b2x_sh[n], bB = b2x_sh[n + 1];
                        const float wA = wx2_sh[n], wB = wx2_sh[n + 1];
                        #pragma unroll
                        for (int mt = 0; mt < 2; mt++) {
                            px[2 * mt + 0] = fmaf(fmaxf(c2q[mt][nl][0] + bA, 0.f), wA,
                                             fmaf(fmaxf(c2q[mt][nl][1] + bB, 0.f), wB,
                                                  px[2 * mt + 0]));
                            px[2 * mt + 1] = fmaf(fmaxf(c2q[mt][nl][2] + bA, 0.f), wA,
                                             fmaf(fmaxf(c2q[mt][nl][3] + bB, 0.f), wB,
                                                  px[2 * mt + 1]));
                        }
                    }
                }
            }

            // reduce px across the 4 lanes sharing td4, then coord update
            #pragma unroll
            for (int i = 0; i < 4; i++) {
                px[i] += __shfl_xor_sync(0xffffffffu, px[i], 1);
                px[i] += __shfl_xor_sync(0xffffffffu, px[i], 2);
                px[i] += bx2v;
            }
            if (tm4 == 0) {
                #pragma unroll
                for (int i = 0; i < 4; i++)
                    px_sh[w * 32 + td4 + 8 * i] = px[i];
            }
            __syncwarp();
            {
                int e = w * 32 + lane;
                float p = px_sh[e];
                float sx = unit_sh[e][0] * p;
                float sy = unit_sh[e][1] * p;
                float sz = unit_sh[e][2] * p;
                #pragma unroll
                for (int o = 16; o > 0; o >>= 1) {
                    sx += __shfl_xor_sync(0xffffffffu, sx, o);
                    sy += __shfl_xor_sync(0xffffffffu, sy, o);
                    sz += __shfl_xor_sync(0xffffffffu, sz, o);
                }
                if (lane == 0) {
                    out_coords[node * 3 + 0] = coords[node * 3 + 0] + sx * (1.f / 32.f);
                    out_coords[node * 3 + 1] = coords[node * 3 + 1] + sy * (1.f / 32.f);
                    out_coords[node * 3 + 2] = coords[node * 3 + 2] + sz * (1.f / 32.f);
                }
            }
        }
        __syncthreads();
    }
}

// ---------------------------------------------------------------------------
// K3: node update MLP with W2 folded.  8 nodes per block, 128 threads.
// ---------------------------------------------------------------------------
__global__ __launch_bounds__(128) void k_node(
    const float* __restrict__ emb,
    const float* __restrict__ mask,
    const float* __restrict__ wh1, const float* __restrict__ bh1,
    const float* __restrict__ wh2, const float* __restrict__ bh2,
    float* __restrict__ out_emb)
{
    __shared__ float esh[8][128];
    __shared__ float hsh[8][128];
    __shared__ float ph[8][128];
    __shared__ float msk[8];
    const int c = threadIdx.x;
    const int n0 = blockIdx.x * 8;

    if (c < 8) msk[c] = mask[n0 + c];
    __syncthreads();
    #pragma unroll
    for (int i = 0; i < 8; i++) {
        esh[i][c] = emb[(n0 + i) * 128 + c];
        hsh[i][c] = g_hsum[(n0 + i) * 128 + c] * (msk[i] * (1.f / 32.f));
    }
    __syncthreads();

    float acc[8];
    {
        float bc = bh1[c];
        float bv = g_bvec[c];
        #pragma unroll
        for (int i = 0; i < 8; i++) acc[i] = bc + msk[i] * bv;
        #pragma unroll 4
        for (int k = 0; k < 128; k += 2) {
            float wa0 = wh1[(k + 0) * 128 + c];
            float wa1 = wh1[(k + 1) * 128 + c];
            float wb0 = g_w2h[(k + 0) * 128 + c];
            float wb1 = g_w2h[(k + 1) * 128 + c];
            #pragma unroll
            for (int i = 0; i < 8; i++) {
                acc[i] = fmaf(esh[i][k],     wa0,
                         fmaf(esh[i][k + 1], wa1,
                         fmaf(hsh[i][k],     wb0,
                         fmaf(hsh[i][k + 1], wb1, acc[i]))));
            }
        }
        #pragma unroll
        for (int i = 0; i < 8; i++) ph[i][c] = fmaxf(acc[i], 0.f);
    }
    __syncthreads();

    float acc2[8];
    {
        float bc = bh2[c];
        #pragma unroll
        for (int i = 0; i < 8; i++) acc2[i] = bc;
        #pragma unroll 4
        for (int p = 0; p < 128; p += 4) {
            float w0  = wh2[(p + 0) * 128 + c];
            float w1v = wh2[(p + 1) * 128 + c];
            float w2v = wh2[(p + 2) * 128 + c];
            float w3  = wh2[(p + 3) * 128 + c];
            #pragma unroll
            for (int i = 0; i < 8; i++) {
                float4 hv = *(const float4*)&ph[i][p];
                acc2[i] = fmaf(hv.x, w0,
                          fmaf(hv.y, w1v,
                          fmaf(hv.z, w2v,
                          fmaf(hv.w, w3, acc2[i]))));
            }
        }
    }
    #pragma unroll
    for (int i = 0; i < 8; i++)
        out_emb[(n0 + i) * 128 + c] = esh[i][c] + acc2[i];
}

// ---------------------------------------------------------------------------
extern "C" void kernel_launch(void* const* d_in, const int* in_sizes, int n_in,
                              void* d_out, int out_size)
{
    const float* emb    = (const float*)d_in[0];
    const float* coords = (const float*)d_in[1];
    const float* mask   = (const float*)d_in[2];
    const float* edges  = (const float*)d_in[3];
    const float* we_w1  = (const float*)d_in[4];
    const float* we_b1  = (const float*)d_in[5];
    const float* we_w2  = (const float*)d_in[6];
    const float* we_b2  = (const float*)d_in[7];
    const float* wx_w1  = (const float*)d_in[8];
    const float* wx_b1  = (const float*)d_in[9];
    const float* wx_w2  = (const float*)d_in[10];
    const float* wx_b2  = (const float*)d_in[11];
    const float* wh_w1  = (const float*)d_in[12];
    const float* wh_b1  = (const float*)d_in[13];
    const float* wh_w2  = (const float*)d_in[14];
    const float* wh_b2  = (const float*)d_in[15];
    const int*   ids    = (const int*)d_in[16];

    float* out_emb    = (float*)d_out;
    float* out_coords = (float*)d_out + (size_t)BN * 128;

    static int attr_set = 0;
    if (!attr_set) {
        cudaFuncSetAttribute(k_edge,
                             cudaFuncAttributeMaxDynamicSharedMemorySize,
                             WIMG_BYTES);
        attr_set = 1;
    }

    k_fold<<<8, 128>>>(we_w2, we_b2, wx_w1, wx_b1, wh_w1);
    k_prep<<<96, 256>>>(we_w1);
    k_proj<<<BN / 8, 128>>>(emb, we_w1);

    k_edge<<<EDGE_GRID, 384, WIMG_BYTES>>>(coords, edges, we_b1,
                                           wx_w2, wx_b2, ids, out_coords);

    k_node<<<BN / 8, 128>>>(emb, mask, wh_w1, wh_b1, wh_w2, wh_b2, out_emb);
}

// round 9
// speedup vs baseline: 1.2371x; 1.1438x over previous
#include <cuda_runtime.h>
#include <cuda_fp16.h>
#include <math.h>
#include <stdint.h>

// Problem constants
#define Bz 8
#define Nn 1024
#define Mm 32
#define BN (Bz*Nn)            // 8192
#define KFREQ (-0.6140226914650789f)   // -log(10000)/15

#define EDGE_GRID 148
#define WARPS_PER_CTA 12
#define NODES_PER_ITER (EDGE_GRID * WARPS_PER_CTA)   // 1776
#define NITER 5                                       // ceil(8192/1776)

// Weight image layout (bytes): B1 | B2   (plain fp16, no split)
// B1: [128 n][64 k], row stride 72 fp16 (144B)  -> 18432 B
// B2: [128 n][128 k], row stride 136 fp16 (272B) -> 34816 B
#define OFF_B1 0
#define OFF_B2 18432
#define WIMG_BYTES 53248

// ---------------------------------------------------------------------------
// Scratch
// ---------------------------------------------------------------------------
__device__ float g_p1[BN*128];     // emb @ W1[0:128]
__device__ float g_p2[BN*128];     // emb @ W1[128:256]
__device__ float g_hsum[BN*128];   // sum_j relu-h
__device__ float g_w2h[128*128];   // W2 @ Wh1[128:256]
__device__ float g_b2x[128];       // b2 @ Wx1 + bx1
__device__ float g_bvec[128];      // b2 @ Wh1[128:256]
__device__ uint4 g_Bimg[WIMG_BYTES/16];

// ---------------------------------------------------------------------------
// helpers
// ---------------------------------------------------------------------------
__device__ __forceinline__ uint32_t s2u(const void* p) {
    uint32_t a;
    asm("{ .reg .u64 t; cvta.to.shared.u64 t, %1; cvt.u32.u64 %0, t; }"
        : "=r"(a) : "l"(p));
    return a;
}
__device__ __forceinline__ void ldmx4(uint32_t& r0, uint32_t& r1,
                                      uint32_t& r2, uint32_t& r3, uint32_t addr) {
    asm volatile("ldmatrix.sync.aligned.m8n8.x4.shared.b16 {%0,%1,%2,%3}, [%4];"
                 : "=r"(r0), "=r"(r1), "=r"(r2), "=r"(r3) : "r"(addr));
}
__device__ __forceinline__ void mma16816(float* c, const uint32_t* a,
                                         uint32_t b0, uint32_t b1) {
    asm volatile(
        "mma.sync.aligned.m16n8k16.row.col.f32.f16.f16.f32 "
        "{%0,%1,%2,%3}, {%4,%5,%6,%7}, {%8,%9}, {%0,%1,%2,%3};"
        : "+f"(c[0]), "+f"(c[1]), "+f"(c[2]), "+f"(c[3])
        : "r"(a[0]), "r"(a[1]), "r"(a[2]), "r"(a[3]), "r"(b0), "r"(b1));
}
// pack: lower half = f0, upper = f1
__device__ __forceinline__ uint32_t packhf(float f0, float f1) {
    uint32_t r;
    asm("cvt.rn.f16x2.f32 %0, %1, %2;" : "=r"(r) : "f"(f1), "f"(f0));
    return r;
}

// ---------------------------------------------------------------------------
// K-1: fold + weight-image prep in one kernel.
//   W2x = W2@Wx1 -> written directly as fp16 B2 image (n-major, stride 136)
//   W2h = W2@Wh1b -> g_w2h (fp32, node kernel)
//   B1 image from we_w1 rows 256..319
//   Block 0: folded bias vectors.
// ---------------------------------------------------------------------------
__global__ __launch_bounds__(128) void k_fold(
    const float* __restrict__ w2,  const float* __restrict__ b2,
    const float* __restrict__ wx1, const float* __restrict__ bx1,
    const float* __restrict__ wh1, const float* __restrict__ w1)
{
    __shared__ float w2sh[16][128];
    unsigned char* img = (unsigned char*)g_Bimg;
    const int c = threadIdx.x;
    const int d0 = blockIdx.x * 16;

    #pragma unroll
    for (int i = 0; i < 16; i++)
        w2sh[i][c] = w2[(d0 + i) * 128 + c];
    __syncthreads();

    float a1[16], a2[16];
    #pragma unroll
    for (int i = 0; i < 16; i++) { a1[i] = 0.f; a2[i] = 0.f; }

    #pragma unroll 2
    for (int k = 0; k < 128; k++) {
        float wA = wx1[k * 128 + c];
        float wB = wh1[(128 + k) * 128 + c];
        #pragma unroll
        for (int i = 0; i < 16; i++) {
            float v = w2sh[i][k];
            a1[i] = fmaf(v, wA, a1[i]);
            a2[i] = fmaf(v, wB, a2[i]);
        }
    }
    #pragma unroll
    for (int i = 0; i < 16; i++) {
        // B2 image entry: n = c, k = d0+i  (stride 136 fp16 = 272 B)
        *(__half*)(img + OFF_B2 + (uint32_t)c * 272 + (uint32_t)(d0 + i) * 2)
            = __float2half_rn(a1[i]);
        g_w2h[(d0 + i) * 128 + c] = a2[i];
    }

    // B1 image: 8192 entries over 8 blocks x 128 threads = 8 per thread
    #pragma unroll
    for (int j = 0; j < 8; j++) {
        int e = blockIdx.x * 1024 + j * 128 + c;
        int n = e & 127, k = e >> 7;           // k 0..63
        *(__half*)(img + OFF_B1 + (uint32_t)n * 144 + (uint32_t)k * 2)
            = __float2half_rn(w1[(256 + k) * 128 + n]);
    }

    if (blockIdx.x == 0) {
        float s1 = bx1[c], s2 = 0.f;
        for (int k = 0; k < 128; k++) {
            float bk = b2[k];
            s1 = fmaf(bk, wx1[k * 128 + c], s1);
            s2 = fmaf(bk, wh1[(128 + k) * 128 + c], s2);
        }
        g_b2x[c]  = s1;
        g_bvec[c] = s2;
    }
}

// ---------------------------------------------------------------------------
// K0: per-node projections p1, p2.  8 nodes per block, 128 threads.
// ---------------------------------------------------------------------------
__global__ __launch_bounds__(128) void k_proj(
    const float* __restrict__ emb, const float* __restrict__ w1)
{
    __shared__ float esh[8][128];
    const int c = threadIdx.x;
    const int n0 = blockIdx.x * 8;

    #pragma unroll
    for (int i = 0; i < 8; i++)
        esh[i][c] = emb[(n0 + i) * 128 + c];
    __syncthreads();

    float a1[8], a2[8];
    #pragma unroll
    for (int i = 0; i < 8; i++) { a1[i] = 0.f; a2[i] = 0.f; }

    #pragma unroll 4
    for (int d = 0; d < 128; d++) {
        float wA = w1[d * 128 + c];
        float wB = w1[(128 + d) * 128 + c];
        #pragma unroll
        for (int i = 0; i < 8; i++) {
            float e = esh[i][d];
            a1[i] = fmaf(e, wA, a1[i]);
            a2[i] = fmaf(e, wB, a2[i]);
        }
    }
    #pragma unroll
    for (int i = 0; i < 8; i++) {
        g_p1[(n0 + i) * 128 + c] = a1[i];
        g_p2[(n0 + i) * 128 + c] = a2[i];
    }
}

// ---------------------------------------------------------------------------
// K1: HMMA edge kernel.  384 threads (12 warps), warp = node.
// Plain fp16 weights (no split): 1 ldmatrix.x4 + 4 MMAs per fragment pair.
// ---------------------------------------------------------------------------
__global__ __launch_bounds__(384, 1) void k_edge(
    const float* __restrict__ coords,
    const float* __restrict__ edges,
    const float* __restrict__ b1g,
    const float* __restrict__ wx2, const float* __restrict__ bx2,
    const int* __restrict__ ids,
    float* __restrict__ out_coords)
{
    extern __shared__ unsigned char wsm[];     // weight image
    const uint32_t sb  = s2u(wsm);
    const uint32_t b1A = sb + OFF_B1;
    const uint32_t b2A = sb + OFF_B2;

    __shared__ float dist_sh[384];
    __shared__ float unit_sh[384][3];
    __shared__ int   jid_sh[384];
    __shared__ float px_sh[384];
    __shared__ float b1_sh[128], b2x_sh[128], wx2_sh[128], fr_sh[16];

    const int tid  = threadIdx.x;
    const int w    = tid >> 5;
    const int lane = tid & 31;
    const int td4  = lane >> 2;
    const int tm4  = lane & 3;

    { // weight image gmem -> smem (52KB)
        uint4* dst = (uint4*)wsm;
        for (int i = tid; i < WIMG_BYTES / 16; i += 384) dst[i] = g_Bimg[i];
    }
    if (tid < 128) {
        b1_sh[tid]  = b1g[tid];
        b2x_sh[tid] = g_b2x[tid];
        wx2_sh[tid] = wx2[tid];
    }
    if (tid < 16) fr_sh[tid] = expf((float)tid * KFREQ);
    __syncthreads();

    const float fr0 = fr_sh[2 * tm4],     fr1 = fr_sh[2 * tm4 + 1];
    const float fr2 = fr_sh[2 * tm4 + 8], fr3 = fr_sh[2 * tm4 + 9];
    const float bx2v = bx2[0];

    const int qsel  = lane >> 3;
    const int ntoff = qsel >> 1;
    const int khalf = qsel & 1;

    for (int it = 0; it < NITER; it++) {
        const int nodebase = it * NODES_PER_ITER + blockIdx.x * WARPS_PER_CTA;

        // per-edge setup: dist, unit, gathered neighbor id (1 thread/edge)
        {
            int nd = nodebase + (tid >> 5);
            if (nd < BN) {
                int m = tid & 31;
                int jabs = ((nd >> 10) << 10) + ids[nd * 32 + m];
                jid_sh[tid] = jabs;
                float dx = coords[nd * 3 + 0] - coords[jabs * 3 + 0];
                float dy = coords[nd * 3 + 1] - coords[jabs * 3 + 1];
                float dz = coords[nd * 3 + 2] - coords[jabs * 3 + 2];
                float d = sqrtf(dx * dx + dy * dy + dz * dz);
                dist_sh[tid] = d;
                float inv = (d > 0.f) ? (1.f / d) : 0.f;
                unit_sh[tid][0] = dx * inv;
                unit_sh[tid][1] = dy * inv;
                unit_sh[tid][2] = dz * inv;
            }
        }
        __syncthreads();

        const int node = nodebase + w;
        if (node < BN) {
            float dloc[4];
            #pragma unroll
            for (int i = 0; i < 4; i++) dloc[i] = dist_sh[w * 32 + td4 + 8 * i];

            // A fragments for GEMM1 (kept across both N-halves): 32 regs
            uint32_t ahi[4][2][4];
            #pragma unroll
            for (int kt = 0; kt < 4; kt++) {
                #pragma unroll
                for (int i = 0; i < 4; i++) {
                    float v0, v1, v2, v3;
                    if (kt == 0) {
                        v0 = __sinf(dloc[i] * fr0); v1 = __sinf(dloc[i] * fr1);
                        v2 = __sinf(dloc[i] * fr2); v3 = __sinf(dloc[i] * fr3);
                    } else if (kt == 1) {
                        v0 = __cosf(dloc[i] * fr0); v1 = __cosf(dloc[i] * fr1);
                        v2 = __cosf(dloc[i] * fr2); v3 = __cosf(dloc[i] * fr3);
                    } else {
                        const float* ep = edges
                            + (size_t)(node * 32 + td4 + 8 * i) * 32
                            + (kt - 2) * 16 + 2 * tm4;
                        float2 va = *(const float2*)ep;
                        float2 vb = *(const float2*)(ep + 8);
                        v0 = va.x; v1 = va.y; v2 = vb.x; v3 = vb.y;
                    }
                    int mt = i >> 1, s = i & 1;
                    ahi[kt][mt][s]     = packhf(v0, v1);
                    ahi[kt][mt][2 + s] = packhf(v2, v3);
                }
            }

            // ---------------- GEMM1 + epilogue1, two N-halves ----------------
            uint32_t a2[2][8][4];
            #pragma unroll
            for (int half = 0; half < 2; half++) {
                float c1h[2][8][4];
                #pragma unroll
                for (int mt = 0; mt < 2; mt++)
                #pragma unroll
                for (int nt = 0; nt < 8; nt++)
                #pragma unroll
                for (int q = 0; q < 4; q++) c1h[mt][nt][q] = 0.f;

                #pragma unroll
                for (int kt = 0; kt < 4; kt++) {
                    #pragma unroll
                    for (int nt2 = 0; nt2 < 4; nt2++) {
                        const int ntq = half * 8 + 2 * nt2 + ntoff;
                        uint32_t off = (uint32_t)((ntq * 8 + (lane & 7)) * 72
                                                  + kt * 16 + khalf * 8) * 2;
                        uint32_t p0, p1, p2, p3;
                        ldmx4(p0, p1, p2, p3, b1A + off);
                        #pragma unroll
                        for (int mt = 0; mt < 2; mt++) {
                            mma16816(c1h[mt][2 * nt2 + 0], ahi[kt][mt], p0, p1);
                            mma16816(c1h[mt][2 * nt2 + 1], ahi[kt][mt], p2, p3);
                        }
                    }
                }

                // epilogue1 for this half: nt = half*8 + ntl
                #pragma unroll
                for (int kt2l = 0; kt2l < 4; kt2l++) {
                    #pragma unroll
                    for (int sub = 0; sub < 2; sub++) {
                        const int ntl = 2 * kt2l + sub;
                        const int n0c = (half * 8 + ntl) * 8 + 2 * tm4;
                        float2 pa = *(const float2*)(g_p1 + (size_t)node * 128 + n0c);
                        const float bb0 = b1_sh[n0c], bb1 = b1_sh[n0c + 1];
                        float hs0 = 0.f, hs1 = 0.f;
                        #pragma unroll
                        for (int mt = 0; mt < 2; mt++) {
                            #pragma unroll
                            for (int mh = 0; mh < 2; mh++) {
                                int j = jid_sh[w * 32 + td4 + 8 * (2 * mt + mh)];
                                float2 p2v = *(const float2*)(g_p2 + (size_t)j * 128 + n0c);
                                float h0 = fmaxf(c1h[mt][ntl][2 * mh + 0] + pa.x + p2v.x + bb0, 0.f);
                                float h1 = fmaxf(c1h[mt][ntl][2 * mh + 1] + pa.y + p2v.y + bb1, 0.f);
                                hs0 += h0; hs1 += h1;
                                a2[mt][half * 4 + kt2l][mh + 2 * sub] = packhf(h0, h1);
                            }
                        }
                        // reduce hsum over the warp's 32 rows (lanes sharing tm4)
                        #pragma unroll
                        for (int o = 4; o < 32; o <<= 1) {
                            hs0 += __shfl_xor_sync(0xffffffffu, hs0, o);
                            hs1 += __shfl_xor_sync(0xffffffffu, hs1, o);
                        }
                        if (td4 == 0) {
                            g_hsum[(size_t)node * 128 + n0c]     = hs0;
                            g_hsum[(size_t)node * 128 + n0c + 1] = hs1;
                        }
                    }
                }
            }

            // ---------------- GEMM2 in N-quarters: C2 = h @ W2x ----------------
            float px[4] = {0.f, 0.f, 0.f, 0.f};
            #pragma unroll
            for (int half = 0; half < 2; half++) {
                #pragma unroll
                for (int q4 = 0; q4 < 2; q4++) {
                    float c2q[2][4][4];
                    #pragma unroll
                    for (int mt = 0; mt < 2; mt++)
                    #pragma unroll
                    for (int nl = 0; nl < 4; nl++)
                    #pragma unroll
                    for (int q = 0; q < 4; q++) c2q[mt][nl][q] = 0.f;

                    #pragma unroll
                    for (int kt2 = 0; kt2 < 8; kt2++) {
                        #pragma unroll
                        for (int nl2 = 0; nl2 < 2; nl2++) {
                            const int ntq = half * 8 + q4 * 4 + 2 * nl2 + ntoff;
                            uint32_t off = (uint32_t)((ntq * 8 + (lane & 7)) * 136
                                                      + kt2 * 16 + khalf * 8) * 2;
                            uint32_t p0, p1, p2, p3;
                            ldmx4(p0, p1, p2, p3, b2A + off);
                            #pragma unroll
                            for (int mt = 0; mt < 2; mt++) {
                                mma16816(c2q[mt][2 * nl2 + 0], a2[mt][kt2], p0, p1);
                                mma16816(c2q[mt][2 * nl2 + 1], a2[mt][kt2], p2, p3);
                            }
                        }
                    }
                    // epilogue2 quarter: t = relu(c2 + b2x); px += t * wx2
                    #pragma unroll
                    for (int nl = 0; nl < 4; nl++) {
                        const int n = half * 64 + q4 * 32 + nl * 8 + 2 * tm4;
                        const float bA = b2x_sh[n], bB = b2x_sh[n + 1];
                        const float wA = wx2_sh[n], wB = wx2_sh[n + 1];
                        #pragma unroll
                        for (int mt = 0; mt < 2; mt++) {
                            px[2 * mt + 0] = fmaf(fmaxf(c2q[mt][nl][0] + bA, 0.f), wA,
                                             fmaf(fmaxf(c2q[mt][nl][1] + bB, 0.f), wB,
                                                  px[2 * mt + 0]));
                            px[2 * mt + 1] = fmaf(fmaxf(c2q[mt][nl][2] + bA, 0.f), wA,
                                             fmaf(fmaxf(c2q[mt][nl][3] + bB, 0.f), wB,
                                                  px[2 * mt + 1]));
                        }
                    }
                }
            }

            // reduce px across the 4 lanes sharing td4, then coord update
            #pragma unroll
            for (int i = 0; i < 4; i++) {
                px[i] += __shfl_xor_sync(0xffffffffu, px[i], 1);
                px[i] += __shfl_xor_sync(0xffffffffu, px[i], 2);
                px[i] += bx2v;
            }
            if (tm4 == 0) {
                #pragma unroll
                for (int i = 0; i < 4; i++)
                    px_sh[w * 32 + td4 + 8 * i] = px[i];
            }
            __syncwarp();
            {
                int e = w * 32 + lane;
                float p = px_sh[e];
                float sx = unit_sh[e][0] * p;
                float sy = unit_sh[e][1] * p;
                float sz = unit_sh[e][2] * p;
                #pragma unroll
                for (int o = 16; o > 0; o >>= 1) {
                    sx += __shfl_xor_sync(0xffffffffu, sx, o);
                    sy += __shfl_xor_sync(0xffffffffu, sy, o);
                    sz += __shfl_xor_sync(0xffffffffu, sz, o);
                }
                if (lane == 0) {
                    out_coords[node * 3 + 0] = coords[node * 3 + 0] + sx * (1.f / 32.f);
                    out_coords[node * 3 + 1] = coords[node * 3 + 1] + sy * (1.f / 32.f);
                    out_coords[node * 3 + 2] = coords[node * 3 + 2] + sz * (1.f / 32.f);
                }
            }
        }
        __syncthreads();
    }
}

// ---------------------------------------------------------------------------
// K3: node update MLP with W2 folded.  8 nodes per block, 128 threads.
// ---------------------------------------------------------------------------
__global__ __launch_bounds__(128) void k_node(
    const float* __restrict__ emb,
    const float* __restrict__ mask,
    const float* __restrict__ wh1, const float* __restrict__ bh1,
    const float* __restrict__ wh2, const float* __restrict__ bh2,
    float* __restrict__ out_emb)
{
    __shared__ float esh[8][128];
    __shared__ float hsh[8][128];
    __shared__ float ph[8][128];
    __shared__ float msk[8];
    const int c = threadIdx.x;
    const int n0 = blockIdx.x * 8;

    if (c < 8) msk[c] = mask[n0 + c];
    __syncthreads();
    #pragma unroll
    for (int i = 0; i < 8; i++) {
        esh[i][c] = emb[(n0 + i) * 128 + c];
        hsh[i][c] = g_hsum[(n0 + i) * 128 + c] * (msk[i] * (1.f / 32.f));
    }
    __syncthreads();

    float acc[8];
    {
        float bc = bh1[c];
        float bv = g_bvec[c];
        #pragma unroll
        for (int i = 0; i < 8; i++) acc[i] = bc + msk[i] * bv;
        #pragma unroll 4
        for (int k = 0; k < 128; k += 2) {
            float wa0 = wh1[(k + 0) * 128 + c];
            float wa1 = wh1[(k + 1) * 128 + c];
            float wb0 = g_w2h[(k + 0) * 128 + c];
            float wb1 = g_w2h[(k + 1) * 128 + c];
            #pragma unroll
            for (int i = 0; i < 8; i++) {
                acc[i] = fmaf(esh[i][k],     wa0,
                         fmaf(esh[i][k + 1], wa1,
                         fmaf(hsh[i][k],     wb0,
                         fmaf(hsh[i][k + 1], wb1, acc[i]))));
            }
        }
        #pragma unroll
        for (int i = 0; i < 8; i++) ph[i][c] = fmaxf(acc[i], 0.f);
    }
    __syncthreads();

    float acc2[8];
    {
        float bc = bh2[c];
        #pragma unroll
        for (int i = 0; i < 8; i++) acc2[i] = bc;
        #pragma unroll 4
        for (int p = 0; p < 128; p += 4) {
            float w0  = wh2[(p + 0) * 128 + c];
            float w1v = wh2[(p + 1) * 128 + c];
            float w2v = wh2[(p + 2) * 128 + c];
            float w3  = wh2[(p + 3) * 128 + c];
            #pragma unroll
            for (int i = 0; i < 8; i++) {
                float4 hv = *(const float4*)&ph[i][p];
                acc2[i] = fmaf(hv.x, w0,
                          fmaf(hv.y, w1v,
                          fmaf(hv.z, w2v,
                          fmaf(hv.w, w3, acc2[i]))));
            }
        }
    }
    #pragma unroll
    for (int i = 0; i < 8; i++)
        out_emb[(n0 + i) * 128 + c] = esh[i][c] + acc2[i];
}

// ---------------------------------------------------------------------------
extern "C" void kernel_launch(void* const* d_in, const int* in_sizes, int n_in,
                              void* d_out, int out_size)
{
    const float* emb    = (const float*)d_in[0];
    const float* coords = (const float*)d_in[1];
    const float* mask   = (const float*)d_in[2];
    const float* edges  = (const float*)d_in[3];
    const float* we_w1  = (const float*)d_in[4];
    const float* we_b1  = (const float*)d_in[5];
    const float* we_w2  = (const float*)d_in[6];
    const float* we_b2  = (const float*)d_in[7];
    const float* wx_w1  = (const float*)d_in[8];
    const float* wx_b1  = (const float*)d_in[9];
    const float* wx_w2  = (const float*)d_in[10];
    const float* wx_b2  = (const float*)d_in[11];
    const float* wh_w1  = (const float*)d_in[12];
    const float* wh_b1  = (const float*)d_in[13];
    const float* wh_w2  = (const float*)d_in[14];
    const float* wh_b2  = (const float*)d_in[15];
    const int*   ids    = (const int*)d_in[16];

    float* out_emb    = (float*)d_out;
    float* out_coords = (float*)d_out + (size_t)BN * 128;

    static int attr_set = 0;
    if (!attr_set) {
        cudaFuncSetAttribute(k_edge,
                             cudaFuncAttributeMaxDynamicSharedMemorySize,
                             WIMG_BYTES);
        attr_set = 1;
    }

    k_fold<<<8, 128>>>(we_w2, we_b2, wx_w1, wx_b1, wh_w1, we_w1);
    k_proj<<<BN / 8, 128>>>(emb, we_w1);

    k_edge<<<EDGE_GRID, 384, WIMG_BYTES>>>(coords, edges, we_b1,
                                           wx_w2, wx_b2, ids, out_coords);

    k_node<<<BN / 8, 128>>>(emb, mask, wh_w1, wh_b1, wh_w2, wh_b2, out_emb);
}